// round 16
// baseline (speedup 1.0000x reference)
#include <cuda_runtime.h>
#include <cuda_fp16.h>
#include <cstdint>
#include <cstddef>

#define BB  16
#define LL  1536
#define DD  512
#define DFF 2048
#define BLD (BB*LL*DD)
#define M_TOTAL (BB*LL)

// tiles: 128x128 CTA, BK = 64 halves (128 bytes/row), 8 warps of 64x32
#define BM 128
#define BN 128
#define A_TILE 16384
#define STAGE_BYTES (2*A_TILE)
#define NST_L 3
#define NST_S 6
#define SMEM_L (NST_L*STAGE_BYTES)   // 98304
#define SMEM_S (NST_S*STAGE_BYTES)   // 196608

// ---------------- device scratch ----------------
__device__ float  g_S[BLD];
__device__ float  g_T[BLD];
__device__ float  g_R[BB*LL];
__device__ float  g_SW[BB*8];
__device__ int    g_IDX[8];
__device__ __half g_hXS[BLD];
__device__ __half g_hXW[BLD];
__device__ __half g_hQ[BLD];
__device__ __half g_hK[BLD];
__device__ __half g_hV[BLD];
__device__ __half g_hS[BLD];
__device__ __half g_hO[BLD];
__device__ __half g_hW1[BLD];
__device__ __half g_hT[BLD];
__device__ __half g_hH[(size_t)BB*LL*DFF];
__device__ __half g_hWa[4*DD*DD];
__device__ __half g_hWb[4*DD*DD];
__device__ __half g_hWc[4*DD*DD];
__device__ __half g_hWT1[3*DD*DD];
__device__ __half g_hWT2[3*DD*DD];
__device__ __half g_hC1[(size_t)DFF*DD];
__device__ __half g_hC2[(size_t)DD*DFF];

// ---------------- static stream/event resources (created at program load) ----------------
struct CudaRes {
    cudaStream_t s1, s2;
    cudaEvent_t evRoot, evXW, evPrep, evW1, evEmb, evQ1, evC2, evQ3;
    CudaRes() {
        cudaStreamCreateWithFlags(&s1, cudaStreamNonBlocking);
        cudaStreamCreateWithFlags(&s2, cudaStreamNonBlocking);
        cudaEventCreateWithFlags(&evRoot, cudaEventDisableTiming);
        cudaEventCreateWithFlags(&evXW,   cudaEventDisableTiming);
        cudaEventCreateWithFlags(&evPrep, cudaEventDisableTiming);
        cudaEventCreateWithFlags(&evW1,   cudaEventDisableTiming);
        cudaEventCreateWithFlags(&evEmb,  cudaEventDisableTiming);
        cudaEventCreateWithFlags(&evQ1,   cudaEventDisableTiming);
        cudaEventCreateWithFlags(&evC2,   cudaEventDisableTiming);
        cudaEventCreateWithFlags(&evQ3,   cudaEventDisableTiming);
    }
};
static CudaRes g_res;

// ---------------- PTX helpers ----------------
__device__ __forceinline__ uint32_t smem_u32(const void* p) {
    uint32_t a;
    asm("{ .reg .u64 t; cvta.to.shared.u64 t, %1; cvt.u32.u64 %0, t; }" : "=r"(a) : "l"(p));
    return a;
}
__device__ __forceinline__ void cp16(uint32_t s, const void* g) {
    asm volatile("cp.async.cg.shared.global [%0], [%1], 16;" :: "r"(s), "l"(g));
}
__device__ __forceinline__ void cp_commit() {
    asm volatile("cp.async.commit_group;" ::: "memory");
}
template<int N> __device__ __forceinline__ void cp_wait() {
    asm volatile("cp.async.wait_group %0;" :: "n"(N) : "memory");
}
__device__ __forceinline__ void cp_wait_dyn(int allow) {
    if      (allow >= 4) cp_wait<4>();
    else if (allow == 3) cp_wait<3>();
    else if (allow == 2) cp_wait<2>();
    else if (allow == 1) cp_wait<1>();
    else                 cp_wait<0>();
}
__device__ __forceinline__ void mma_f16(float* d, const uint32_t* a, const uint32_t* b) {
    asm volatile("mma.sync.aligned.m16n8k16.row.col.f32.f16.f16.f32 "
        "{%0,%1,%2,%3}, {%4,%5,%6,%7}, {%8,%9}, {%0,%1,%2,%3};"
        : "+f"(d[0]), "+f"(d[1]), "+f"(d[2]), "+f"(d[3])
        : "r"(a[0]), "r"(a[1]), "r"(a[2]), "r"(a[3]), "r"(b[0]), "r"(b[1]));
}
__device__ __forceinline__ void ldsm4(uint32_t& r0, uint32_t& r1, uint32_t& r2, uint32_t& r3,
                                      uint32_t a) {
    asm volatile("ldmatrix.sync.aligned.m8n8.x4.shared.b16 {%0,%1,%2,%3}, [%4];"
        : "=r"(r0), "=r"(r1), "=r"(r2), "=r"(r3) : "r"(a));
}
__device__ __forceinline__ uint32_t swz16(uint32_t o) { return o ^ ((o >> 3) & 0x70); }

// =====================================================================
// fp16 HMMA GEMM: C = sum_pass A_pass @ B_pass^T (+bias)(+resid f32)(relu)
// MODE 0: f32 out.  MODE 1: half out.  MODE 2: dual f32+half.  MODE 3: split half dsts.
// NST: pipeline stages (prefetch depth NST-1).  MINB: min blocks per SM.
// =====================================================================
template<int MODE, int NST, int MINB>
__global__ __launch_bounds__(256, MINB)
void gemm_g(const __half* __restrict__ A, const __half* __restrict__ B,
            float* __restrict__ Cf, __half* __restrict__ Ch0,
            __half* __restrict__ Ch1, __half* __restrict__ Ch2,
            const float* __restrict__ bias, const float* __restrict__ resid,
            int N, int K, int npasses, int relu)
{
    extern __shared__ char smem[];
    const uint32_t sb = smem_u32(smem);
    const int tid = threadIdx.x;
    const int lane = tid & 31, wid = tid >> 5;
    const int wr = wid & 1, wc = wid >> 1;
    const int m0 = blockIdx.y * BM, n0 = blockIdx.x * BN;
    const int kSteps = K / 64;
    const int T = npasses * kSteps;

    int arow[4], achk[4];
#pragma unroll
    for (int u = 0; u < 4; u++) { int q = tid*4 + u; arow[u] = q >> 3; achk[u] = q & 7; }

    auto load_stage = [&](int t) {
        int pass = (npasses > 1) ? (t / kSteps) : 0;
        int k0 = (t - pass * kSteps) * 64;
        uint32_t sA = sb + (t % NST) * STAGE_BYTES;
        uint32_t sB = sA + A_TILE;
        const __half* Bp = B + (size_t)pass * N * K;
#pragma unroll
        for (int u = 0; u < 4; u++) {
            int m = m0 + arow[u], rg = m;
            if (npasses > 1) {
                int b = m / LL, l = m - b * LL;
                l += pass - 1;
                if (l < 0) l += LL; else if (l >= LL) l -= LL;
                rg = b * LL + l;
            }
            cp16(sA + swz16(arow[u]*128 + achk[u]*16),
                 A + (size_t)rg * K + k0 + achk[u]*8);
        }
#pragma unroll
        for (int u = 0; u < 4; u++)
            cp16(sB + swz16(arow[u]*128 + achk[u]*16),
                 Bp + (size_t)(n0 + arow[u]) * K + k0 + achk[u]*8);
        cp_commit();
    };

#pragma unroll
    for (int s = 0; s < NST-1; s++)
        if (s < T) load_stage(s);

    float acc[4][4][4];
#pragma unroll
    for (int i = 0; i < 4; i++)
#pragma unroll
        for (int j = 0; j < 4; j++)
#pragma unroll
            for (int r = 0; r < 4; r++) acc[i][j][r] = 0.f;

    const int sw = lane & 7;
    int aoffs[4], boffs[2];
#pragma unroll
    for (int i = 0; i < 4; i++)
        aoffs[i] = (wr*64 + i*16 + ((lane >> 3) & 1)*8 + sw) * 128;
#pragma unroll
    for (int jp = 0; jp < 2; jp++)
        boffs[jp] = (wc*32 + jp*16 + ((lane >> 4) & 1)*8 + sw) * 128;
    const int aC = lane >> 4;
    const int bC = (lane >> 3) & 1;

    for (int t = 0; t < T; t++) {
        int rem = T - 1 - t;
        int allow = rem < (NST-2) ? rem : (NST-2);
        cp_wait_dyn(allow);
        __syncthreads();
        if (t + NST-1 < T) load_stage(t + NST-1);

        uint32_t sA = sb + (t % NST) * STAGE_BYTES;
        uint32_t sB = sA + A_TILE;
#pragma unroll
        for (int s16 = 0; s16 < 4; s16++) {
            uint32_t af[4][4], bf[4][2];
            uint32_t ach = (uint32_t)(((s16*2 + aC) ^ sw) << 4);
            uint32_t bch = (uint32_t)(((s16*2 + bC) ^ sw) << 4);
#pragma unroll
            for (int i = 0; i < 4; i++)
                ldsm4(af[i][0], af[i][1], af[i][2], af[i][3], sA + aoffs[i] + ach);
#pragma unroll
            for (int jp = 0; jp < 2; jp++)
                ldsm4(bf[2*jp][0], bf[2*jp][1], bf[2*jp+1][0], bf[2*jp+1][1],
                      sB + boffs[jp] + bch);
#pragma unroll
            for (int i = 0; i < 4; i++)
#pragma unroll
                for (int j = 0; j < 4; j++)
                    mma_f16(acc[i][j], af[i], bf[j]);
        }
    }

    // epilogue
#pragma unroll
    for (int i = 0; i < 4; i++) {
        int mrow = m0 + wr*64 + i*16 + (lane >> 2);
#pragma unroll
        for (int j = 0; j < 4; j++) {
            int n = n0 + wc*32 + j*8 + 2*(lane & 3);
#pragma unroll
            for (int h = 0; h < 2; h++) {
                int mm = mrow + h*8;
                float vx = acc[i][j][2*h+0], vy = acc[i][j][2*h+1];
                if (bias)  { vx += bias[n]; vy += bias[n+1]; }
                if (resid) {
                    float2 rv = *reinterpret_cast<const float2*>(&resid[(size_t)mm*N + n]);
                    vx += rv.x; vy += rv.y;
                }
                if (relu) { vx = fmaxf(vx, 0.f); vy = fmaxf(vy, 0.f); }
                if (MODE == 0 || MODE == 2) {
                    float2 v; v.x = vx; v.y = vy;
                    *reinterpret_cast<float2*>(&Cf[(size_t)mm*N + n]) = v;
                }
                if (MODE == 1 || MODE == 2) {
                    __half2 hv = __floats2half2_rn(vx, vy);
                    *reinterpret_cast<__half2*>(&Ch0[(size_t)mm*N + n]) = hv;
                }
                if (MODE == 3) {
                    __half* dst = (n < 512) ? Ch0 : ((n < 1024) ? Ch1 : Ch2);
                    int col = n & 511;
                    __half2 hv = __floats2half2_rn(vx, vy);
                    *reinterpret_cast<__half2*>(&dst[(size_t)mm*512 + col]) = hv;
                }
            }
        }
    }
}

// =====================================================================
// corr: r[b,tau] += diagonal sums of Q_b K_b^T over 128x128 tiles (fp16)
// deep-prefetch NST_S, occ 1
// =====================================================================
__global__ __launch_bounds__(256, 1)
void corr_mm(const __half* __restrict__ Q, const __half* __restrict__ Kb,
             float* __restrict__ r)
{
    extern __shared__ char smem[];
    const uint32_t sb = smem_u32(smem);
    const int tid = threadIdx.x;
    const int lane = tid & 31, wid = tid >> 5;
    const int wr = wid & 1, wc = wid >> 1;
    const int b = blockIdx.z;
    const int i0 = blockIdx.y * BM, j0 = blockIdx.x * BN;
    const __half* Qb = Q + (size_t)b * LL * DD;
    const __half* KB = Kb + (size_t)b * LL * DD;
    const int T = DD / 64;   // 8

    int arow[4], achk[4];
#pragma unroll
    for (int u = 0; u < 4; u++) { int q = tid*4 + u; arow[u] = q >> 3; achk[u] = q & 7; }

    auto load_stage = [&](int t) {
        int k0 = t * 64;
        uint32_t sA = sb + (t % NST_S) * STAGE_BYTES;
        uint32_t sB = sA + A_TILE;
#pragma unroll
        for (int u = 0; u < 4; u++)
            cp16(sA + swz16(arow[u]*128 + achk[u]*16),
                 Qb + (size_t)(i0 + arow[u]) * DD + k0 + achk[u]*8);
#pragma unroll
        for (int u = 0; u < 4; u++)
            cp16(sB + swz16(arow[u]*128 + achk[u]*16),
                 KB + (size_t)(j0 + arow[u]) * DD + k0 + achk[u]*8);
        cp_commit();
    };

#pragma unroll
    for (int s = 0; s < NST_S-1; s++)
        if (s < T) load_stage(s);

    float acc[4][4][4];
#pragma unroll
    for (int i = 0; i < 4; i++)
#pragma unroll
        for (int j = 0; j < 4; j++)
#pragma unroll
            for (int q = 0; q < 4; q++) acc[i][j][q] = 0.f;

    const int sw = lane & 7;
    int aoffs[4], boffs[2];
#pragma unroll
    for (int i = 0; i < 4; i++)
        aoffs[i] = (wr*64 + i*16 + ((lane >> 3) & 1)*8 + sw) * 128;
#pragma unroll
    for (int jp = 0; jp < 2; jp++)
        boffs[jp] = (wc*32 + jp*16 + ((lane >> 4) & 1)*8 + sw) * 128;
    const int aC = lane >> 4;
    const int bC = (lane >> 3) & 1;

    for (int t = 0; t < T; t++) {
        int rem = T - 1 - t;
        int allow = rem < (NST_S-2) ? rem : (NST_S-2);
        cp_wait_dyn(allow);
        __syncthreads();
        if (t + NST_S-1 < T) load_stage(t + NST_S-1);

        uint32_t sA = sb + (t % NST_S) * STAGE_BYTES;
        uint32_t sB = sA + A_TILE;
#pragma unroll
        for (int s16 = 0; s16 < 4; s16++) {
            uint32_t af[4][4], bf[4][2];
            uint32_t ach = (uint32_t)(((s16*2 + aC) ^ sw) << 4);
            uint32_t bch = (uint32_t)(((s16*2 + bC) ^ sw) << 4);
#pragma unroll
            for (int i = 0; i < 4; i++)
                ldsm4(af[i][0], af[i][1], af[i][2], af[i][3], sA + aoffs[i] + ach);
#pragma unroll
            for (int jp = 0; jp < 2; jp++)
                ldsm4(bf[2*jp][0], bf[2*jp][1], bf[2*jp+1][0], bf[2*jp+1][1],
                      sB + boffs[jp] + bch);
#pragma unroll
            for (int i = 0; i < 4; i++)
#pragma unroll
                for (int j = 0; j < 4; j++)
                    mma_f16(acc[i][j], af[i], bf[j]);
        }
    }

    __syncthreads();
    float* Cs = (float*)smem;   // 128 x 130
#pragma unroll
    for (int i = 0; i < 4; i++) {
        int mrow = wr*64 + i*16 + (lane >> 2);
#pragma unroll
        for (int j = 0; j < 4; j++) {
            int n = wc*32 + j*8 + 2*(lane & 3);
#pragma unroll
            for (int h = 0; h < 2; h++) {
                float2 v; v.x = acc[i][j][2*h+0]; v.y = acc[i][j][2*h+1];
                *reinterpret_cast<float2*>(&Cs[(mrow + h*8)*130 + n]) = v;
            }
        }
    }
    __syncthreads();

    if (tid < 255) {
        int d = tid - 127;
        int ilo = d > 0 ? d : 0;
        int ihi = d < 0 ? 127 + d : 127;
        float s = 0.f;
        for (int i = ilo; i <= ihi; i++) s += Cs[i*130 + (i - d)];
        int tau = (i0 - j0 + d) % LL;
        if (tau < 0) tau += LL;
        atomicAdd(&r[(size_t)b * LL + tau], s);
    }
}

// ---------------- fused prep: all weight conversions + R zero in ONE kernel ----------------
__global__ void prep_all_kernel(
    const float* __restrict__ wc1_W, const float* __restrict__ attn_W,
    const float* __restrict__ wc2_W, const float* __restrict__ conv1_W,
    const float* __restrict__ conv2_W, const float* __restrict__ wc1_proj,
    const float* __restrict__ wc2_proj,
    __half* __restrict__ hWa, __half* __restrict__ hWb, __half* __restrict__ hWc,
    __half* __restrict__ hC1, __half* __restrict__ hC2,
    __half* __restrict__ hWT1, __half* __restrict__ hWT2,
    float* __restrict__ R)
{
    int gid = blockIdx.x * 256 + threadIdx.x;
    if (gid < 1310720) {
        int rgn = gid / 262144;
        int i = gid - rgn * 262144;
        const float* src; __half* dst;
        switch (rgn) {
        case 0: src = wc1_W;  dst = hWa; break;
        case 1: src = attn_W; dst = hWb; break;
        case 2: src = wc2_W;  dst = hWc; break;
        case 3: src = conv1_W; dst = hC1; break;
        default: src = conv2_W; dst = hC2; break;
        }
        float4 v = reinterpret_cast<const float4*>(src)[i];
        reinterpret_cast<__half2*>(dst)[2*i]   = __floats2half2_rn(v.x, v.y);
        reinterpret_cast<__half2*>(dst)[2*i+1] = __floats2half2_rn(v.z, v.w);
    } else if (gid < 2883584) {
        int j = gid - 1310720;
        const float* src = wc1_proj; __half* dst = hWT1;
        if (j >= 786432) { j -= 786432; src = wc2_proj; dst = hWT2; }
        int p = j / (DD*DD);
        int rr = j - p * (DD*DD);
        int n = rr >> 9, k = rr & 511;
        dst[j] = __float2half_rn(src[n * (DD*3) + k * 3 + p]);
    } else if (gid < 2889728) {
        int j = gid - 2883584;
        reinterpret_cast<float4*>(R)[j] = make_float4(0.f, 0.f, 0.f, 0.f);
    }
}

__global__ void zero_kernel(float* p, int n)
{
    int i = blockIdx.x * 256 + threadIdx.x;
    if (i < n) p[i] = 0.f;
}

__global__ void cvt_h_kernel(const float* __restrict__ x, __half* __restrict__ y, int n4)
{
    int i = blockIdx.x * 256 + threadIdx.x;
    if (i < n4) {
        float4 v = reinterpret_cast<const float4*>(x)[i];
        reinterpret_cast<__half2*>(y)[2*i]   = __floats2half2_rn(v.x, v.y);
        reinterpret_cast<__half2*>(y)[2*i+1] = __floats2half2_rn(v.z, v.w);
    }
}

__global__ void topk_kernel(const float* __restrict__ r, int* __restrict__ gidx,
                            float* __restrict__ gsw)
{
    __shared__ float gv[LL];
    __shared__ float rv[256];
    __shared__ int   ri[256];
    __shared__ int   sidx[7];
    const int tid = threadIdx.x;

    for (int t = tid; t < LL; t += 256) {
        float s = 0.f;
        for (int b = 0; b < BB; b++) s += r[(size_t)b*LL + t];
        gv[t] = s;
    }
    __syncthreads();

    for (int it = 0; it < 7; it++) {
        float bv = -3.4e38f; int bi = 0;
        for (int t = tid; t < LL; t += 256) {
            float v = gv[t];
            if (v > bv) { bv = v; bi = t; }
        }
        rv[tid] = bv; ri[tid] = bi;
        __syncthreads();
        for (int s = 128; s > 0; s >>= 1) {
            if (tid < s) {
                if (rv[tid+s] > rv[tid] ||
                    (rv[tid+s] == rv[tid] && ri[tid+s] < ri[tid])) {
                    rv[tid] = rv[tid+s]; ri[tid] = ri[tid+s];
                }
            }
            __syncthreads();
        }
        if (tid == 0) { sidx[it] = ri[0]; gv[ri[0]] = -3.4e38f; }
        __syncthreads();
    }

    if (tid < 7) gidx[tid] = sidx[tid];
    if (tid < BB) {
        float w[7], m = -3.4e38f;
        for (int i = 0; i < 7; i++) {
            w[i] = r[(size_t)tid*LL + sidx[i]] * (1.0f / (float)DD);
            m = fmaxf(m, w[i]);
        }
        float sum = 0.f;
        for (int i = 0; i < 7; i++) { w[i] = expf(w[i] - m); sum += w[i]; }
        float inv = 1.0f / sum;
        for (int i = 0; i < 7; i++) gsw[tid*7 + i] = w[i] * inv;
    }
}

__global__ __launch_bounds__(256)
void agg_h_kernel(const __half* __restrict__ V, __half* __restrict__ O,
                  const int* __restrict__ idxp, const float* __restrict__ swp)
{
    int g = blockIdx.x * 256 + threadIdx.x;
    int d8 = g & 63;
    int l  = (g >> 6) % LL;
    int b  = g / (LL * 64);

    int   idx[7];
    float w[7];
#pragma unroll
    for (int i = 0; i < 7; i++) { idx[i] = idxp[i]; w[i] = swp[b*7 + i]; }

    const uint4* Vb = reinterpret_cast<const uint4*>(V + (size_t)b * LL * DD);
    float acc[8];
#pragma unroll
    for (int q = 0; q < 8; q++) acc[q] = 0.f;
#pragma unroll
    for (int i = 0; i < 7; i++) {
        int ls = l + idx[i];
        if (ls >= LL) ls -= LL;
        uint4 v = Vb[(size_t)ls * 64 + d8];
        const __half2* hp = reinterpret_cast<const __half2*>(&v);
#pragma unroll
        for (int q = 0; q < 4; q++) {
            float2 f = __half22float2(hp[q]);
            acc[2*q+0] += w[i] * f.x;
            acc[2*q+1] += w[i] * f.y;
        }
    }
    uint4 out;
    __half2* op = reinterpret_cast<__half2*>(&out);
#pragma unroll
    for (int q = 0; q < 4; q++) op[q] = __floats2half2_rn(acc[2*q], acc[2*q+1]);
    reinterpret_cast<uint4*>(O)[g] = out;
}

// series_decomp, chunk 24 per block for 4x parallelism
#define MA_CH 24
__global__ __launch_bounds__(128)
void movavg_kernel(const float* __restrict__ X, float* __restrict__ out,
                   __half* __restrict__ outh)
{
    const int b  = blockIdx.y;
    const int l0 = blockIdx.x * MA_CH;
    const int d4 = threadIdx.x;
    const float4* x = reinterpret_cast<const float4*>(X + (size_t)b * LL * DD) + d4;
    float4* o = reinterpret_cast<float4*>(out + (size_t)b * LL * DD) + d4;
    __half2* oh = outh ? (reinterpret_cast<__half2*>(outh + (size_t)b * LL * DD) + d4*2)
                       : (__half2*)nullptr;

    float4 s = {0.f, 0.f, 0.f, 0.f};
    for (int j = -12; j <= 12; j++) {
        int lc = l0 + j;
        if (lc < 0) lc = 0;
        if (lc > LL-1) lc = LL-1;
        float4 v = x[(size_t)lc * 128];
        s.x += v.x; s.y += v.y; s.z += v.z; s.w += v.w;
    }
    const float inv = 1.0f / 25.0f;
    for (int t = 0; t < MA_CH; t++) {
        int l = l0 + t;
        float4 xc = x[(size_t)l * 128];
        float4 rr;
        rr.x = xc.x - s.x * inv; rr.y = xc.y - s.y * inv;
        rr.z = xc.z - s.z * inv; rr.w = xc.w - s.w * inv;
        o[(size_t)l * 128] = rr;
        if (outh) {
            oh[(size_t)l * 256]     = __floats2half2_rn(rr.x, rr.y);
            oh[(size_t)l * 256 + 1] = __floats2half2_rn(rr.z, rr.w);
        }
        int la = l + 13; if (la > LL-1) la = LL-1;
        int lr = l - 12; if (lr < 0)    lr = 0;
        float4 va = x[(size_t)la * 128];
        float4 vr = x[(size_t)lr * 128];
        s.x += va.x - vr.x; s.y += va.y - vr.y;
        s.z += va.z - vr.z; s.w += va.w - vr.w;
    }
}

// ---------------- host orchestration ----------------
static void cvt_h(const float* x, __half* y, size_t n, cudaStream_t st)
{
    cvt_h_kernel<<<(int)((n/4 + 255)/256), 256, 0, st>>>(x, y, (int)(n/4));
}

// shortk=1: deep-prefetch NST_S occ1; shortk=0: NST_L occ2
static void launch_gemm(int mode, int shortk, const __half* A, const __half* B,
                        float* Cf, __half* h0, __half* h1, __half* h2,
                        const float* bias, const float* resid,
                        int N, int K, int npasses, int relu, cudaStream_t st)
{
    dim3 grid(N / BN, M_TOTAL / BM);
    if (shortk) {
        switch (mode) {
        case 0: gemm_g<0,NST_S,1><<<grid,256,SMEM_S,st>>>(A,B,Cf,h0,h1,h2,bias,resid,N,K,npasses,relu); break;
        case 1: gemm_g<1,NST_S,1><<<grid,256,SMEM_S,st>>>(A,B,Cf,h0,h1,h2,bias,resid,N,K,npasses,relu); break;
        case 2: gemm_g<2,NST_S,1><<<grid,256,SMEM_S,st>>>(A,B,Cf,h0,h1,h2,bias,resid,N,K,npasses,relu); break;
        default: gemm_g<3,NST_S,1><<<grid,256,SMEM_S,st>>>(A,B,Cf,h0,h1,h2,bias,resid,N,K,npasses,relu); break;
        }
    } else {
        switch (mode) {
        case 0: gemm_g<0,NST_L,2><<<grid,256,SMEM_L,st>>>(A,B,Cf,h0,h1,h2,bias,resid,N,K,npasses,relu); break;
        default: gemm_g<1,NST_L,2><<<grid,256,SMEM_L,st>>>(A,B,Cf,h0,h1,h2,bias,resid,N,K,npasses,relu); break;
        }
    }
}

extern "C" void kernel_launch(void* const* d_in, const int* in_sizes, int n_in,
                              void* d_out, int out_size)
{
    const float* x_s      = (const float*)d_in[0];
    const float* x_w      = (const float*)d_in[1];
    const float* wc1_W    = (const float*)d_in[2];
    const float* wc1_b    = (const float*)d_in[3];
    const float* wc2_W    = (const float*)d_in[4];
    const float* wc2_b    = (const float*)d_in[5];
    const float* attn_W   = (const float*)d_in[6];
    const float* attn_b   = (const float*)d_in[7];
    const float* wc1_proj = (const float*)d_in[8];
    const float* wc2_proj = (const float*)d_in[9];
    const float* conv1_W  = (const float*)d_in[10];
    const float* conv2_W  = (const float*)d_in[11];

    float* out_res = (float*)d_out;
    float* out_w   = out_res + BLD;

    cudaFuncSetAttribute((gemm_g<0,NST_S,1>), cudaFuncAttributeMaxDynamicSharedMemorySize, SMEM_S);
    cudaFuncSetAttribute((gemm_g<1,NST_S,1>), cudaFuncAttributeMaxDynamicSharedMemorySize, SMEM_S);
    cudaFuncSetAttribute((gemm_g<2,NST_S,1>), cudaFuncAttributeMaxDynamicSharedMemorySize, SMEM_S);
    cudaFuncSetAttribute((gemm_g<3,NST_S,1>), cudaFuncAttributeMaxDynamicSharedMemorySize, SMEM_S);
    cudaFuncSetAttribute((gemm_g<0,NST_L,2>), cudaFuncAttributeMaxDynamicSharedMemorySize, SMEM_L);
    cudaFuncSetAttribute((gemm_g<1,NST_L,2>), cudaFuncAttributeMaxDynamicSharedMemorySize, SMEM_L);
    cudaFuncSetAttribute(corr_mm, cudaFuncAttributeMaxDynamicSharedMemorySize, SMEM_S);

    float *S, *T, *R, *SW; int* IDX;
    __half *hXS, *hXW, *hQ, *hK, *hV, *hS, *hO, *hW1, *hT, *hH;
    __half *hWa, *hWb, *hWc, *hWT1, *hWT2, *hC1, *hC2;
    cudaGetSymbolAddress((void**)&S,    g_S);
    cudaGetSymbolAddress((void**)&T,    g_T);
    cudaGetSymbolAddress((void**)&R,    g_R);
    cudaGetSymbolAddress((void**)&SW,   g_SW);
    cudaGetSymbolAddress((void**)&IDX,  g_IDX);
    cudaGetSymbolAddress((void**)&hXS,  g_hXS);
    cudaGetSymbolAddress((void**)&hXW,  g_hXW);
    cudaGetSymbolAddress((void**)&hQ,   g_hQ);
    cudaGetSymbolAddress((void**)&hK,   g_hK);
    cudaGetSymbolAddress((void**)&hV,   g_hV);
    cudaGetSymbolAddress((void**)&hS,   g_hS);
    cudaGetSymbolAddress((void**)&hO,   g_hO);
    cudaGetSymbolAddress((void**)&hW1,  g_hW1);
    cudaGetSymbolAddress((void**)&hT,   g_hT);
    cudaGetSymbolAddress((void**)&hH,   g_hH);
    cudaGetSymbolAddress((void**)&hWa,  g_hWa);
    cudaGetSymbolAddress((void**)&hWb,  g_hWb);
    cudaGetSymbolAddress((void**)&hWc,  g_hWc);
    cudaGetSymbolAddress((void**)&hWT1, g_hWT1);
    cudaGetSymbolAddress((void**)&hWT2, g_hWT2);
    cudaGetSymbolAddress((void**)&hC1,  g_hC1);
    cudaGetSymbolAddress((void**)&hC2,  g_hC2);

    cudaStream_t s1 = g_res.s1, s2 = g_res.s2;
    dim3 cg(LL/BN, LL/BM, BB);
    dim3 mg(LL/MA_CH, BB);

    // ---- root fork ----
    cudaEventRecord(g_res.evRoot, 0);

    // s2: fused weight prep (+ R zero for attn1)
    cudaStreamWaitEvent(s2, g_res.evRoot, 0);
    prep_all_kernel<<<(2889728 + 255)/256, 256, 0, s2>>>(
        wc1_W, attn_W, wc2_W, conv1_W, conv2_W, wc1_proj, wc2_proj,
        hWa, hWb, hWc, hC1, hC2, hWT1, hWT2, R);
    cudaEventRecord(g_res.evPrep, s2);

    // stream 0: input conversions
    cvt_h(x_w, hXW, BLD, 0);
    cudaEventRecord(g_res.evXW, 0);
    cvt_h(x_s, hXS, BLD, 0);

    // s2: Q1 projection — overlaps KV1 on stream 0
    cudaStreamWaitEvent(s2, g_res.evXW, 0);
    launch_gemm(1, 1, hXW, hWa, nullptr, hQ, nullptr, nullptr, wc1_b, nullptr,
                DD, DD, 1, 0, s2);
    cudaEventRecord(g_res.evQ1, s2);

    cudaStreamWaitEvent(0, g_res.evPrep, 0);

    // stream 0: KV1
    launch_gemm(3, 1, hXS, hWa + DD*DD, nullptr, hK, hV, nullptr, wc1_b + DD, nullptr,
                2*DD, DD, 1, 0, 0);

    // corr1
    cudaStreamWaitEvent(0, g_res.evQ1, 0);
    corr_mm<<<cg, 256, SMEM_S>>>(hQ, hK, R);

    // s1: embeds (overlap with attention chain)
    cudaStreamWaitEvent(s1, g_res.evXW, 0);
    cudaStreamWaitEvent(s1, g_res.evPrep, 0);
    launch_gemm(1, 0, hXW, hWT1, nullptr, hW1, nullptr, nullptr, nullptr, nullptr,
                DD, DD, 3, 0, s1);
    cudaEventRecord(g_res.evW1, s1);
    launch_gemm(0, 0, hW1, hWT2, out_w, nullptr, nullptr, nullptr, nullptr, nullptr,
                DD, DD, 3, 0, s1);
    cudaEventRecord(g_res.evEmb, s1);

    // stream 0: rest of attn1
    topk_kernel<<<1, 256>>>(R, IDX, SW);
    agg_h_kernel<<<BLD/8/256, 256>>>(hV, hO, IDX, SW);
    launch_gemm(2, 1, hO, hWa + 3*DD*DD, S, hS, nullptr, nullptr,
                wc1_b + 3*DD, x_s, DD, DD, 1, 0, 0);

    // attn2: self-attention on hS (fused QKV)
    launch_gemm(3, 1, hS, hWb, nullptr, hQ, hK, hV, attn_b, nullptr, 3*DD, DD, 1, 0, 0);
    zero_kernel<<<(BB*LL + 255)/256, 256>>>(R, BB*LL);
    corr_mm<<<cg, 256, SMEM_S>>>(hQ, hK, R);
    cudaEventRecord(g_res.evC2, 0);
    topk_kernel<<<1, 256>>>(R, IDX, SW);
    agg_h_kernel<<<BLD/8/256, 256>>>(hV, hO, IDX, SW);
    launch_gemm(0, 1, hO, hWb + 3*DD*DD, T, nullptr, nullptr, nullptr,
                attn_b + 3*DD, S, DD, DD, 1, 0, 0);

    // series_decomp: S = decomp(T), dual store
    movavg_kernel<<<mg, 128>>>(T, S, hS);

    // s2: Q3 projection — waits corr2 (hQ reuse) & embed1
    cudaStreamWaitEvent(s2, g_res.evC2, 0);
    cudaStreamWaitEvent(s2, g_res.evW1, 0);
    launch_gemm(1, 1, hW1, hWc, nullptr, hQ, nullptr, nullptr, wc2_b, nullptr,
                DD, DD, 1, 0, s2);
    cudaEventRecord(g_res.evQ3, s2);

    // stream 0: attn3 KV, corr3
    launch_gemm(3, 1, hS, hWc + DD*DD, nullptr, hK, hV, nullptr, wc2_b + DD, nullptr,
                2*DD, DD, 1, 0, 0);
    zero_kernel<<<(BB*LL + 255)/256, 256>>>(R, BB*LL);
    cudaStreamWaitEvent(0, g_res.evQ3, 0);
    corr_mm<<<cg, 256, SMEM_S>>>(hQ, hK, R);
    topk_kernel<<<1, 256>>>(R, IDX, SW);
    agg_h_kernel<<<BLD/8/256, 256>>>(hV, hO, IDX, SW);
    launch_gemm(2, 1, hO, hWc + 3*DD*DD, T, hT, nullptr, nullptr,
                wc2_b + 3*DD, S, DD, DD, 1, 0, 0);

    // FFN
    launch_gemm(1, 1, hT, hC1, nullptr, hH, nullptr, nullptr, nullptr, nullptr,
                DFF, DD, 1, 1, 0);
    launch_gemm(0, 0, hH, hC2, S, nullptr, nullptr, nullptr, nullptr, T,
                DD, DFF, 1, 0, 0);

    // final series_decomp
    movavg_kernel<<<mg, 128>>>(S, out_res, nullptr);

    // join embed stream
    cudaStreamWaitEvent(0, g_res.evEmb, 0);
}